// round 14
// baseline (speedup 1.0000x reference)
#include <cuda_runtime.h>
#include <cuda_fp16.h>

// Problem constants (fixed shapes for this problem)
#define NB 4       // batch
#define CC 32      // channels (C_in == C_out)
#define NN 10000   // nodes
#define TT 12      // time steps
#define EMAX 160000
#define FF (CC*TT)          // 384 features per (b,n)
#define BNT (NB*NN*TT)      // 480000
#define TOT (NB*NN*FF)      // 15,360,000
#define NROW (NB*FF)        // 1536 halfs per node (all batches)
#define NROWU4 (NROW/8)     // 192 uint4 per node row (fp16)

// Scratch (device globals; no allocation allowed)
// Layout: node-major so one warp serves all batches of a node.
__device__ __align__(16) __half g_h  [TOT];   // [N][B][T][C] fp16
__device__ __align__(16) __half g_agg[TOT];   // [N][B][T][C] fp16 (stats taken from fp32 regs)
__device__ int    g_deg[NN+1];
__device__ int    g_row[NN+1];
__device__ int    g_cur[NN];
__device__ int    g_srcs[EMAX];
__device__ float  g_ws  [EMAX];
__device__ double g_sum [CC];
__device__ double g_sumsq[CC];
__device__ float  g_scale[CC];
__device__ float  g_shift[CC];
// Monotone dtype flag: 0 => int64 edge_index. Never reset per-launch; input is
// constant across graph replays, so the sticky value is deterministic.
__device__ int    g_nz = 0;

// ---------------- init: zero counters + detect edge_index dtype ----------------
// Detect: under int64 layout the high word of every 64-bit slot is 0 (indices
// < 2^31). Under int32 layout those words are arbitrary node indices — never
// all zero across E samples. Reads only the first 2E int32 words (in-bounds
// under both interpretations).
__global__ void k_init(const int* __restrict__ ei, int E) {
    int gid = blockIdx.x * blockDim.x + threadIdx.x;
    if (gid < NN + 1) g_deg[gid] = 0;
    if (gid < CC) { g_sum[gid] = 0.0; g_sumsq[gid] = 0.0; }
    int stride = gridDim.x * blockDim.x;
    int nz = 0;
    for (int i = gid; i < E; i += stride) nz |= ei[2 * i + 1];
    if (__any_sync(0xffffffffu, nz != 0) && (threadIdx.x & 31) == 0)
        g_nz = 1;   // race-free: only ever set to 1
}

__device__ __forceinline__ int load_idx(const void* eiv, long long pos) {
    if (g_nz == 0) return (int)((const long long*)eiv)[pos];
    return ((const int*)eiv)[pos];
}

// ---------------- linear: h[n][b][t][c] = sum_ci x[b][ci][n][t] * W[ci][c] (fp16 out) ----------------
__global__ void k_linear(const float* __restrict__ x, const float* __restrict__ W) {
    __shared__ __align__(16) float ws[CC * CC];
    int tid = threadIdx.x;
    for (int i = tid; i < CC * CC; i += blockDim.x) ws[i] = W[i];
    __syncthreads();

    int gid = blockIdx.x * blockDim.x + tid;   // enumerates (b, n, t) — b major for coalesced x reads
    if (gid >= BNT) return;
    int b = gid / (NN * TT);
    int r = gid % (NN * TT);                   // n*TT + t
    int n = r / TT;
    int t = r % TT;

    const float* xp = x + (size_t)b * CC * NN * TT + r;
    float xv[CC];
#pragma unroll
    for (int c = 0; c < CC; c++) xv[c] = xp[c * (NN * TT)];

    float4 acc[8];
#pragma unroll
    for (int d = 0; d < 8; d++) acc[d] = make_float4(0.f, 0.f, 0.f, 0.f);

    const float4* w4 = (const float4*)ws;      // [c][8] float4 rows of W
#pragma unroll
    for (int c = 0; c < CC; c++) {
        float xc = xv[c];
#pragma unroll
        for (int d = 0; d < 8; d++) {
            float4 w = w4[c * 8 + d];
            acc[d].x = fmaf(xc, w.x, acc[d].x);
            acc[d].y = fmaf(xc, w.y, acc[d].y);
            acc[d].z = fmaf(xc, w.z, acc[d].z);
            acc[d].w = fmaf(xc, w.w, acc[d].w);
        }
    }

    // pack 32 floats -> 32 halfs -> 4 uint4 stores at node-major offset
    uint4* hp = (uint4*)g_h + ((size_t)n * NB + b) * (FF / 8) + t * 4;
#pragma unroll
    for (int j = 0; j < 4; j++) {
        __half2 p0 = __floats2half2_rn(acc[2 * j].x,     acc[2 * j].y);
        __half2 p1 = __floats2half2_rn(acc[2 * j].z,     acc[2 * j].w);
        __half2 p2 = __floats2half2_rn(acc[2 * j + 1].x, acc[2 * j + 1].y);
        __half2 p3 = __floats2half2_rn(acc[2 * j + 1].z, acc[2 * j + 1].w);
        uint4 o;
        o.x = *reinterpret_cast<unsigned*>(&p0);
        o.y = *reinterpret_cast<unsigned*>(&p1);
        o.z = *reinterpret_cast<unsigned*>(&p2);
        o.w = *reinterpret_cast<unsigned*>(&p3);
        hp[j] = o;
    }
}

// ---------------- degree histogram ----------------
__global__ void k_hist(const void* __restrict__ eiv, int E) {
    int e = blockIdx.x * blockDim.x + threadIdx.x;
    if (e >= E) return;
    int dst = load_idx(eiv, (long long)E + e);
    if ((unsigned)dst < NN) atomicAdd(&g_deg[dst], 1);
}

// ---------------- exclusive scan over degrees (single block) ----------------
__global__ void k_scan() {
    __shared__ int sp[1024];
    int tid = threadIdx.x;
    const int CH = (NN + 1023) / 1024;  // 10
    int base = tid * CH;
    int s = 0;
    for (int k = 0; k < CH; k++) { int i = base + k; if (i < NN) s += g_deg[i]; }
    sp[tid] = s;
    __syncthreads();
    for (int off = 1; off < 1024; off <<= 1) {
        int v = (tid >= off) ? sp[tid - off] : 0;
        __syncthreads();
        sp[tid] += v;
        __syncthreads();
    }
    int run = sp[tid] - s;  // exclusive prefix of this chunk
    for (int k = 0; k < CH; k++) {
        int i = base + k;
        if (i < NN) { g_row[i] = run; g_cur[i] = run; run += g_deg[i]; }
    }
    if (tid == 1023) g_row[NN] = sp[1023];
}

// ---------------- fill CSR ----------------
__global__ void k_fill(const void* __restrict__ eiv, const float* __restrict__ ew, int E) {
    int e = blockIdx.x * blockDim.x + threadIdx.x;
    if (e >= E) return;
    int dst = load_idx(eiv, (long long)E + e);
    if ((unsigned)dst >= NN) return;          // matches k_hist skip
    int src = load_idx(eiv, e);
    int p = atomicAdd(&g_cur[dst], 1);
    if ((unsigned)src < NN) {
        g_srcs[p] = src;
        g_ws[p]   = ew[e];
    } else {                                  // keep CSR slot consistent, zero-weight
        g_srcs[p] = 0;
        g_ws[p]   = 0.f;
    }
}

// ---------------- gather + fused BN stats ----------------
// One warp per node, all 4 batches. fp16 source, fp32 accum, fp16 agg store.
// Bias is intentionally dropped: a per-channel constant shift is exactly
// cancelled by the training-mode BatchNorm that follows (y - mean(y)).
__device__ __forceinline__ void fma8(float2* a, uint4 v, float w) {
    unsigned u[4] = { v.x, v.y, v.z, v.w };
#pragma unroll
    for (int k = 0; k < 4; k++) {
        float2 f = __half22float2(*reinterpret_cast<__half2*>(&u[k]));
        a[k].x = fmaf(w, f.x, a[k].x);
        a[k].y = fmaf(w, f.y, a[k].y);
    }
}

// grid is exactly NN/4 blocks of 128 threads (NN % 4 == 0): no inactive warps.
__global__ __launch_bounds__(128) void k_gather() {
    int n    = (blockIdx.x * blockDim.x + threadIdx.x) >> 5;
    int lane = threadIdx.x & 31;

    float2 acc[24];                           // 48 floats = this lane's slice of 4 batch rows
#pragma unroll
    for (int k = 0; k < 24; k++) acc[k] = make_float2(0.f, 0.f);

    int e0 = g_row[n], e1 = g_row[n + 1];
    const uint4* hb = (const uint4*)g_h;

    for (int e = e0; e < e1; e++) {
        float w = g_ws[e];
        const uint4* hr = hb + (size_t)g_srcs[e] * NROWU4;
        uint4 v[6];
#pragma unroll
        for (int j = 0; j < 6; j++) v[j] = hr[lane + 32 * j];   // 6 independent 16B loads
#pragma unroll
        for (int j = 0; j < 6; j++) fma8(&acc[j * 4], v[j], w);
    }

    // store fp16 agg: chunk j covers halfs [8*(lane+32j), +8) = one uint4
    uint4* ap = (uint4*)g_agg + (size_t)n * NROWU4;
#pragma unroll
    for (int j = 0; j < 6; j++) {
        __half2 p0 = __floats2half2_rn(acc[4*j].x,   acc[4*j].y);
        __half2 p1 = __floats2half2_rn(acc[4*j+1].x, acc[4*j+1].y);
        __half2 p2 = __floats2half2_rn(acc[4*j+2].x, acc[4*j+2].y);
        __half2 p3 = __floats2half2_rn(acc[4*j+3].x, acc[4*j+3].y);
        uint4 o;
        o.x = *reinterpret_cast<unsigned*>(&p0);
        o.y = *reinterpret_cast<unsigned*>(&p1);
        o.z = *reinterpret_cast<unsigned*>(&p2);
        o.w = *reinterpret_cast<unsigned*>(&p3);
        ap[lane + 32 * j] = o;
    }

    // fused per-channel stats: float index 8*(lane+32j)+k has channel (8*lane+k)&31,
    // so this lane covers 8 fixed channels: cbase..cbase+7, cbase = 8*(lane&3).
    float s[8], ss[8];
#pragma unroll
    for (int k = 0; k < 8; k++) { s[k] = 0.f; ss[k] = 0.f; }
#pragma unroll
    for (int j = 0; j < 6; j++) {
#pragma unroll
        for (int m = 0; m < 4; m++) {
            float2 v = acc[4 * j + m];
            s [2*m]   += v.x;  ss[2*m]   += v.x * v.x;
            s [2*m+1] += v.y;  ss[2*m+1] += v.y * v.y;
        }
    }
    // lanes sharing lane%4 hold the same channel set: reduce over offsets 16,8,4
#pragma unroll
    for (int off = 16; off >= 4; off >>= 1) {
#pragma unroll
        for (int k = 0; k < 8; k++) {
            s [k] += __shfl_xor_sync(0xffffffffu, s [k], off);
            ss[k] += __shfl_xor_sync(0xffffffffu, ss[k], off);
        }
    }
    __shared__ float sb[CC], ssb[CC];
    if (threadIdx.x < CC) { sb[threadIdx.x] = 0.f; ssb[threadIdx.x] = 0.f; }
    __syncthreads();
    if (lane < 4) {
        int cbase = 8 * lane;
#pragma unroll
        for (int k = 0; k < 8; k++) {
            atomicAdd(&sb [cbase + k], s [k]);
            atomicAdd(&ssb[cbase + k], ss[k]);
        }
    }
    __syncthreads();
    if (threadIdx.x < CC) {
        atomicAdd(&g_sum  [threadIdx.x], (double)sb [threadIdx.x]);
        atomicAdd(&g_sumsq[threadIdx.x], (double)ssb[threadIdx.x]);
    }
}

// ---------------- finalize BN params ----------------
__global__ void k_final(const float* __restrict__ gamma, const float* __restrict__ beta) {
    int c = threadIdx.x;
    if (c < CC) {
        double cnt  = (double)NB * NN * TT;
        double mean = g_sum[c] / cnt;
        double var  = g_sumsq[c] / cnt - mean * mean;
        float sc = gamma[c] * rsqrtf((float)var + 1e-5f);
        g_scale[c] = sc;
        g_shift[c] = beta[c] - (float)mean * sc;
    }
}

// ---------------- transpose + normalize + relu -> out[B][C][N][T] ----------------
#define CHUNK 16
__global__ void k_out(float* __restrict__ out) {
    __shared__ __align__(16) float tile[CHUNK * TT * 33];  // [j=0..191][c padded 33]
    __shared__ float sc[CC], sf[CC];
    int b     = blockIdx.x / (NN / CHUNK);
    int chunk = blockIdx.x % (NN / CHUNK);
    int n0 = chunk * CHUNK;
    int tid = threadIdx.x;
    if (tid < CC) { sc[tid] = g_scale[tid]; sf[tid] = g_shift[tid]; }

    // source rows are node-major fp16: row (node n0+nd, batch b) at ((n0+nd)*NB + b)*FF
    // load as half2 (FF even, pairs stay within a row and a tile row)
    for (int p = tid; p < CHUNK * FF / 2; p += 256) {
        int i  = 2 * p;
        int nd = i / FF;
        int f  = i % FF;
        __half2 hv = *(const __half2*)&g_agg[((size_t)(n0 + nd) * NB + b) * FF + f];
        float2 fv = __half22float2(hv);
        int row = i >> 5, col = i & 31;
        tile[row * 33 + col]     = fv.x;
        tile[row * 33 + col + 1] = fv.y;
    }
    __syncthreads();

    float* ob = out + (size_t)b * CC * NN * TT + n0 * TT;
    const int JD = CHUNK * TT;  // 192
    for (int i = tid; i < CHUNK * FF; i += 256) {
        int c = i / JD;
        int j = i % JD;
        float v = fmaf(tile[j * 33 + c], sc[c], sf[c]);
        ob[(size_t)c * NN * TT + j] = fmaxf(v, 0.f);
    }
}

extern "C" void kernel_launch(void* const* d_in, const int* in_sizes, int n_in,
                              void* d_out, int out_size) {
    const float* x     = (const float*)d_in[0];
    const void*  ei    = (const void*)d_in[1];
    const float* ew    = (const float*)d_in[2];
    const float* W     = (const float*)d_in[3];
    const float* gamma = (const float*)d_in[5];
    const float* beta  = (const float*)d_in[6];
    float* out = (float*)d_out;

    int E = in_sizes[2];   // edge_weight element count == E

    k_init<<<160, 256>>>((const int*)ei, E);
    k_linear<<<(BNT + 255) / 256, 256>>>(x, W);
    k_hist<<<(E + 255) / 256, 256>>>(ei, E);
    k_scan<<<1, 1024>>>();
    k_fill<<<(E + 255) / 256, 256>>>(ei, ew, E);
    k_gather<<<NN / 4, 128>>>();
    k_final<<<1, 32>>>(gamma, beta);
    k_out<<<NB * (NN / CHUNK), 256>>>(out);
}

// round 15
// speedup vs baseline: 1.0351x; 1.0351x over previous
#include <cuda_runtime.h>
#include <cuda_fp16.h>

// Problem constants (fixed shapes for this problem)
#define NB 4       // batch
#define CC 32      // channels (C_in == C_out)
#define NN 10000   // nodes
#define TT 12      // time steps
#define EMAX 160000
#define FF (CC*TT)          // 384 features per (b,n)
#define BNT (NB*NN*TT)      // 480000
#define TOT (NB*NN*FF)      // 15,360,000
#define NROW (NB*FF)        // 1536 halfs per node (all batches)
#define NROWU4 (NROW/8)     // 192 uint4 per node row (fp16)

// Scratch (device globals; no allocation allowed)
// Layout: node-major so one warp serves all batches of a node.
__device__ __align__(16) __half g_h  [TOT];   // [N][B][T][C] fp16
__device__ __align__(16) __half g_agg[TOT];   // [N][B][T][C] fp16 (stats taken from fp32 regs)
__device__ int    g_deg[NN+1];
__device__ int    g_row[NN+1];
__device__ int    g_cur[NN];
__device__ int    g_srcs[EMAX];
__device__ float  g_ws  [EMAX];
__device__ double g_sum [CC];
__device__ double g_sumsq[CC];
__device__ float  g_scale[CC];
__device__ float  g_shift[CC];
// Monotone dtype flag: 0 => int64 edge_index. Never reset per-launch; input is
// constant across graph replays, so the sticky value is deterministic.
__device__ int    g_nz = 0;

// ---------------- init: zero counters + detect edge_index dtype ----------------
// Detect: under int64 layout the high word of every 64-bit slot is 0 (indices
// < 2^31). Under int32 layout those words are arbitrary node indices — never
// all zero across E samples. Reads only the first 2E int32 words (in-bounds
// under both interpretations).
__global__ void k_init(const int* __restrict__ ei, int E) {
    int gid = blockIdx.x * blockDim.x + threadIdx.x;
    if (gid < NN + 1) g_deg[gid] = 0;
    if (gid < CC) { g_sum[gid] = 0.0; g_sumsq[gid] = 0.0; }
    int stride = gridDim.x * blockDim.x;
    int nz = 0;
    for (int i = gid; i < E; i += stride) nz |= ei[2 * i + 1];
    if (__any_sync(0xffffffffu, nz != 0) && (threadIdx.x & 31) == 0)
        g_nz = 1;   // race-free: only ever set to 1
}

__device__ __forceinline__ int load_idx(const void* eiv, long long pos) {
    if (g_nz == 0) return (int)((const long long*)eiv)[pos];
    return ((const int*)eiv)[pos];
}

// ---------------- linear: h[n][b][t][c] = sum_ci x[b][ci][n][t] * W[ci][c] (fp16 out) ----------------
__global__ void k_linear(const float* __restrict__ x, const float* __restrict__ W) {
    __shared__ __align__(16) float ws[CC * CC];
    int tid = threadIdx.x;
    for (int i = tid; i < CC * CC; i += blockDim.x) ws[i] = W[i];
    __syncthreads();

    int gid = blockIdx.x * blockDim.x + tid;   // enumerates (b, n, t) — b major for coalesced x reads
    if (gid >= BNT) return;
    int b = gid / (NN * TT);
    int r = gid % (NN * TT);                   // n*TT + t
    int n = r / TT;
    int t = r % TT;

    const float* xp = x + (size_t)b * CC * NN * TT + r;
    float xv[CC];
#pragma unroll
    for (int c = 0; c < CC; c++) xv[c] = xp[c * (NN * TT)];

    float4 acc[8];
#pragma unroll
    for (int d = 0; d < 8; d++) acc[d] = make_float4(0.f, 0.f, 0.f, 0.f);

    const float4* w4 = (const float4*)ws;      // [c][8] float4 rows of W
#pragma unroll
    for (int c = 0; c < CC; c++) {
        float xc = xv[c];
#pragma unroll
        for (int d = 0; d < 8; d++) {
            float4 w = w4[c * 8 + d];
            acc[d].x = fmaf(xc, w.x, acc[d].x);
            acc[d].y = fmaf(xc, w.y, acc[d].y);
            acc[d].z = fmaf(xc, w.z, acc[d].z);
            acc[d].w = fmaf(xc, w.w, acc[d].w);
        }
    }

    // pack 32 floats -> 32 halfs -> 4 uint4 stores at node-major offset
    uint4* hp = (uint4*)g_h + ((size_t)n * NB + b) * (FF / 8) + t * 4;
#pragma unroll
    for (int j = 0; j < 4; j++) {
        __half2 p0 = __floats2half2_rn(acc[2 * j].x,     acc[2 * j].y);
        __half2 p1 = __floats2half2_rn(acc[2 * j].z,     acc[2 * j].w);
        __half2 p2 = __floats2half2_rn(acc[2 * j + 1].x, acc[2 * j + 1].y);
        __half2 p3 = __floats2half2_rn(acc[2 * j + 1].z, acc[2 * j + 1].w);
        uint4 o;
        o.x = *reinterpret_cast<unsigned*>(&p0);
        o.y = *reinterpret_cast<unsigned*>(&p1);
        o.z = *reinterpret_cast<unsigned*>(&p2);
        o.w = *reinterpret_cast<unsigned*>(&p3);
        hp[j] = o;
    }
}

// ---------------- degree histogram ----------------
__global__ void k_hist(const void* __restrict__ eiv, int E) {
    int e = blockIdx.x * blockDim.x + threadIdx.x;
    if (e >= E) return;
    int dst = load_idx(eiv, (long long)E + e);
    if ((unsigned)dst < NN) atomicAdd(&g_deg[dst], 1);
}

// ---------------- exclusive scan over degrees: 3-phase shuffle scan, 2 barriers ----------------
#define SCH 10  // items per thread; 1024*10 >= NN+1
__global__ void k_scan() {
    int tid  = threadIdx.x;
    int lane = tid & 31;
    int wid  = tid >> 5;
    int base = tid * SCH;

    int v[SCH];
    int s = 0;
#pragma unroll
    for (int k = 0; k < SCH; k++) {
        int i = base + k;
        v[k] = (i < NN) ? g_deg[i] : 0;
        s += v[k];
    }

    // inclusive warp scan of per-thread sums
    int x = s;
#pragma unroll
    for (int off = 1; off < 32; off <<= 1) {
        int t = __shfl_up_sync(0xffffffffu, x, off);
        if (lane >= off) x += t;
    }

    __shared__ int wsum[32];
    if (lane == 31) wsum[wid] = x;
    __syncthreads();
    if (wid == 0) {
        int y = wsum[lane];
#pragma unroll
        for (int off = 1; off < 32; off <<= 1) {
            int t = __shfl_up_sync(0xffffffffu, y, off);
            if (lane >= off) y += t;
        }
        wsum[lane] = y;
    }
    __syncthreads();

    int run = (wid ? wsum[wid - 1] : 0) + x - s;   // exclusive prefix for this thread
#pragma unroll
    for (int k = 0; k < SCH; k++) {
        int i = base + k;
        if (i < NN) { g_row[i] = run; g_cur[i] = run; run += v[k]; }
    }
    if (base <= NN && NN < base + SCH) g_row[NN] = run;  // total (node NN slot)
}

// ---------------- fill CSR ----------------
__global__ void k_fill(const void* __restrict__ eiv, const float* __restrict__ ew, int E) {
    int e = blockIdx.x * blockDim.x + threadIdx.x;
    if (e >= E) return;
    int dst = load_idx(eiv, (long long)E + e);
    if ((unsigned)dst >= NN) return;          // matches k_hist skip
    int src = load_idx(eiv, e);
    int p = atomicAdd(&g_cur[dst], 1);
    if ((unsigned)src < NN) {
        g_srcs[p] = src;
        g_ws[p]   = ew[e];
    } else {                                  // keep CSR slot consistent, zero-weight
        g_srcs[p] = 0;
        g_ws[p]   = 0.f;
    }
}

// ---------------- gather + fused BN stats ----------------
// One warp per node, all 4 batches. fp16 source, fp32 accum, fp16 agg store.
// Bias is intentionally dropped: a per-channel constant shift is exactly
// cancelled by the training-mode BatchNorm that follows (y - mean(y)).
__device__ __forceinline__ void fma8(float2* a, uint4 v, float w) {
    unsigned u[4] = { v.x, v.y, v.z, v.w };
#pragma unroll
    for (int k = 0; k < 4; k++) {
        float2 f = __half22float2(*reinterpret_cast<__half2*>(&u[k]));
        a[k].x = fmaf(w, f.x, a[k].x);
        a[k].y = fmaf(w, f.y, a[k].y);
    }
}

// grid is exactly NN/4 blocks of 128 threads (NN % 4 == 0): no inactive warps.
__global__ __launch_bounds__(128) void k_gather() {
    int n    = (blockIdx.x * blockDim.x + threadIdx.x) >> 5;
    int lane = threadIdx.x & 31;

    float2 acc[24];                           // 48 floats = this lane's slice of 4 batch rows
#pragma unroll
    for (int k = 0; k < 24; k++) acc[k] = make_float2(0.f, 0.f);

    int e0 = g_row[n], e1 = g_row[n + 1];
    const uint4* hb = (const uint4*)g_h;

    for (int e = e0; e < e1; e++) {
        float w = g_ws[e];
        const uint4* hr = hb + (size_t)g_srcs[e] * NROWU4;
        uint4 v[6];
#pragma unroll
        for (int j = 0; j < 6; j++) v[j] = hr[lane + 32 * j];   // 6 independent 16B loads
#pragma unroll
        for (int j = 0; j < 6; j++) fma8(&acc[j * 4], v[j], w);
    }

    // store fp16 agg: chunk j covers halfs [8*(lane+32j), +8) = one uint4
    uint4* ap = (uint4*)g_agg + (size_t)n * NROWU4;
#pragma unroll
    for (int j = 0; j < 6; j++) {
        __half2 p0 = __floats2half2_rn(acc[4*j].x,   acc[4*j].y);
        __half2 p1 = __floats2half2_rn(acc[4*j+1].x, acc[4*j+1].y);
        __half2 p2 = __floats2half2_rn(acc[4*j+2].x, acc[4*j+2].y);
        __half2 p3 = __floats2half2_rn(acc[4*j+3].x, acc[4*j+3].y);
        uint4 o;
        o.x = *reinterpret_cast<unsigned*>(&p0);
        o.y = *reinterpret_cast<unsigned*>(&p1);
        o.z = *reinterpret_cast<unsigned*>(&p2);
        o.w = *reinterpret_cast<unsigned*>(&p3);
        ap[lane + 32 * j] = o;
    }

    // fused per-channel stats: float index 8*(lane+32j)+k has channel (8*lane+k)&31,
    // so this lane covers 8 fixed channels: cbase..cbase+7, cbase = 8*(lane&3).
    float s[8], ss[8];
#pragma unroll
    for (int k = 0; k < 8; k++) { s[k] = 0.f; ss[k] = 0.f; }
#pragma unroll
    for (int j = 0; j < 6; j++) {
#pragma unroll
        for (int m = 0; m < 4; m++) {
            float2 v = acc[4 * j + m];
            s [2*m]   += v.x;  ss[2*m]   += v.x * v.x;
            s [2*m+1] += v.y;  ss[2*m+1] += v.y * v.y;
        }
    }
    // lanes sharing lane%4 hold the same channel set: reduce over offsets 16,8,4
#pragma unroll
    for (int off = 16; off >= 4; off >>= 1) {
#pragma unroll
        for (int k = 0; k < 8; k++) {
            s [k] += __shfl_xor_sync(0xffffffffu, s [k], off);
            ss[k] += __shfl_xor_sync(0xffffffffu, ss[k], off);
        }
    }
    __shared__ float sb[CC], ssb[CC];
    if (threadIdx.x < CC) { sb[threadIdx.x] = 0.f; ssb[threadIdx.x] = 0.f; }
    __syncthreads();
    if (lane < 4) {
        int cbase = 8 * lane;
#pragma unroll
        for (int k = 0; k < 8; k++) {
            atomicAdd(&sb [cbase + k], s [k]);
            atomicAdd(&ssb[cbase + k], ss[k]);
        }
    }
    __syncthreads();
    if (threadIdx.x < CC) {
        atomicAdd(&g_sum  [threadIdx.x], (double)sb [threadIdx.x]);
        atomicAdd(&g_sumsq[threadIdx.x], (double)ssb[threadIdx.x]);
    }
}

// ---------------- finalize BN params ----------------
__global__ void k_final(const float* __restrict__ gamma, const float* __restrict__ beta) {
    int c = threadIdx.x;
    if (c < CC) {
        double cnt  = (double)NB * NN * TT;
        double mean = g_sum[c] / cnt;
        double var  = g_sumsq[c] / cnt - mean * mean;
        float sc = gamma[c] * rsqrtf((float)var + 1e-5f);
        g_scale[c] = sc;
        g_shift[c] = beta[c] - (float)mean * sc;
    }
}

// ---------------- transpose + normalize + relu -> out[B][C][N][T] ----------------
#define CHUNK 16
__global__ void k_out(float* __restrict__ out) {
    __shared__ __align__(16) float tile[CHUNK * TT * 33];  // [j=0..191][c padded 33]
    __shared__ float sc[CC], sf[CC];
    int b     = blockIdx.x / (NN / CHUNK);
    int chunk = blockIdx.x % (NN / CHUNK);
    int n0 = chunk * CHUNK;
    int tid = threadIdx.x;
    if (tid < CC) { sc[tid] = g_scale[tid]; sf[tid] = g_shift[tid]; }

    // source rows are node-major fp16: row (node n0+nd, batch b) at ((n0+nd)*NB + b)*FF
    for (int p = tid; p < CHUNK * FF / 2; p += 256) {
        int i  = 2 * p;
        int nd = i / FF;
        int f  = i % FF;
        __half2 hv = *(const __half2*)&g_agg[((size_t)(n0 + nd) * NB + b) * FF + f];
        float2 fv = __half22float2(hv);
        int row = i >> 5, col = i & 31;
        tile[row * 33 + col]     = fv.x;
        tile[row * 33 + col + 1] = fv.y;
    }
    __syncthreads();

    float* ob = out + (size_t)b * CC * NN * TT + n0 * TT;
    const int JD = CHUNK * TT;  // 192
    for (int i = tid; i < CHUNK * FF; i += 256) {
        int c = i / JD;
        int j = i % JD;
        float v = fmaf(tile[j * 33 + c], sc[c], sf[c]);
        ob[(size_t)c * NN * TT + j] = fmaxf(v, 0.f);
    }
}

extern "C" void kernel_launch(void* const* d_in, const int* in_sizes, int n_in,
                              void* d_out, int out_size) {
    const float* x     = (const float*)d_in[0];
    const void*  ei    = (const void*)d_in[1];
    const float* ew    = (const float*)d_in[2];
    const float* W     = (const float*)d_in[3];
    const float* gamma = (const float*)d_in[5];
    const float* beta  = (const float*)d_in[6];
    float* out = (float*)d_out;

    int E = in_sizes[2];   // edge_weight element count == E

    // Lazily-created side stream + events for fork/join (created once; the
    // captured graph is identical on every call).
    static cudaStream_t s2 = nullptr;
    static cudaEvent_t evFork = nullptr, evJoin = nullptr;
    if (s2 == nullptr) {
        cudaStreamCreateWithFlags(&s2, cudaStreamNonBlocking);
        cudaEventCreateWithFlags(&evFork, cudaEventDisableTiming);
        cudaEventCreateWithFlags(&evJoin, cudaEventDisableTiming);
    }

    // Fork: k_linear (independent of the CSR chain) runs on s2.
    cudaEventRecord(evFork, 0);
    cudaStreamWaitEvent(s2, evFork, 0);
    k_linear<<<(BNT + 255) / 256, 256, 0, s2>>>(x, W);
    cudaEventRecord(evJoin, s2);

    // CSR chain on the main stream.
    k_init<<<160, 256>>>((const int*)ei, E);
    k_hist<<<(E + 255) / 256, 256>>>(ei, E);
    k_scan<<<1, 1024>>>();
    k_fill<<<(E + 255) / 256, 256>>>(ei, ew, E);

    // Join: gather needs both g_h (s2) and the CSR arrays (main stream).
    cudaStreamWaitEvent(0, evJoin, 0);
    k_gather<<<NN / 4, 128>>>();
    k_final<<<1, 32>>>(gamma, beta);
    k_out<<<NB * (NN / CHUNK), 256>>>(out);
}

// round 17
// speedup vs baseline: 1.0371x; 1.0019x over previous
#include <cuda_runtime.h>
#include <cuda_fp16.h>

// Problem constants (fixed shapes for this problem)
#define NB 4       // batch
#define CC 32      // channels (C_in == C_out)
#define NN 10000   // nodes
#define TT 12      // time steps
#define EMAX 160000
#define FF (CC*TT)          // 384 features per (b,n)
#define BNT (NB*NN*TT)      // 480000
#define TOT (NB*NN*FF)      // 15,360,000
#define NROW (NB*FF)        // 1536 halfs per node (all batches)
#define NROWU4 (NROW/8)     // 192 uint4 per node row (fp16)

#define CB  148             // CSR-build grid: one block per SM, all resident
#define CHN 68              // nodes per block chunk: 148*68 = 10064 >= NN

// Scratch (device globals; no allocation allowed)
// Layout: node-major so one warp serves all batches of a node.
__device__ __align__(16) __half g_h  [TOT];   // [N][B][T][C] fp16
__device__ __align__(16) __half g_agg[TOT];   // [N][B][T][C] fp16 (stats from fp32 regs)
__device__ int    g_deg[NN+1];
__device__ int    g_row[NN+1];
__device__ int    g_cur[NN];
__device__ int    g_srcs[EMAX];
__device__ float  g_ws  [EMAX];
__device__ int    g_bsum[CB];
__device__ int    g_boff[CB];
__device__ unsigned g_bar[8];   // grid-barrier counters; reset by k_final each run
__device__ double g_sum [CC];
__device__ double g_sumsq[CC];
__device__ float  g_scale[CC];
__device__ float  g_shift[CC];
// Monotone dtype flag: 0 => int64 edge_index. Never reset; input constant across replays.
__device__ int    g_nz = 0;

__device__ __forceinline__ int load_idx(const void* eiv, long long pos) {
    if (g_nz == 0) return (int)((const long long*)eiv)[pos];
    return ((const int*)eiv)[pos];
}

// DIY grid barrier: all CB blocks are resident (148 blocks x 256 thr, tiny regs/smem),
// so spinning is safe. Counters monotone within a launch; k_final resets them.
__device__ __forceinline__ void grid_barrier(int p) {
    __syncthreads();
    if (threadIdx.x == 0) {
        __threadfence();
        atomicAdd(&g_bar[p], 1u);
        unsigned spins = 0;
        while (*(volatile unsigned*)&g_bar[p] < (unsigned)CB) {
            __nanosleep(64);
            if (++spins > 200000000u) break;   // safety bound (never hit when resident)
        }
    }
    __syncthreads();
}

// ---------------- fused CSR build: zero+detect | hist | 2-level scan | fill ----------------
__global__ __launch_bounds__(256) void k_csr(const void* __restrict__ eiv,
                                             const float* __restrict__ ew, int E) {
    int tid = threadIdx.x;
    int blk = blockIdx.x;
    int gt  = blk * 256 + tid;
    const int GS = CB * 256;

    // Phase A: zero counters + dtype detect (high word of each 64-bit slot;
    // reads only first 2E int32 words — in-bounds under both layouts)
    for (int i = gt; i < NN + 1; i += GS) g_deg[i] = 0;
    if (gt < CC) { g_sum[gt] = 0.0; g_sumsq[gt] = 0.0; }
    {
        const int* e32 = (const int*)eiv;
        int nz = 0;
        for (int i = gt; i < E; i += GS) nz |= e32[2 * i + 1];
        if (__any_sync(0xffffffffu, nz != 0) && (tid & 31) == 0) g_nz = 1;
    }
    grid_barrier(0);

    // Phase B: degree histogram
    for (int e = gt; e < E; e += GS) {
        int dst = load_idx(eiv, (long long)E + e);
        if ((unsigned)dst < NN) atomicAdd(&g_deg[dst], 1);
    }
    grid_barrier(1);

    // Phase C: per-block chunk sums (contiguous CHN nodes per block)
    int lo  = blk * CHN;
    int hi  = min(lo + CHN, NN);
    int cnt = hi > lo ? hi - lo : 0;
    __shared__ int sdeg[CHN];
    __shared__ int bsum;
    if (tid == 0) bsum = 0;
    __syncthreads();
    if (tid < cnt) {
        int v = __ldcg(&g_deg[lo + tid]);   // bypass L1: written by other blocks
        sdeg[tid] = v;
        atomicAdd(&bsum, v);
    }
    __syncthreads();
    if (tid == 0) g_bsum[blk] = bsum;
    grid_barrier(2);

    // Phase D: block 0 scans the CB block sums (exclusive)
    if (blk == 0) {
        __shared__ int sp[256];
        int v = (tid < CB) ? __ldcg(&g_bsum[tid]) : 0;
        sp[tid] = v;
        __syncthreads();
        for (int off = 1; off < 256; off <<= 1) {
            int t2 = (tid >= off) ? sp[tid - off] : 0;
            __syncthreads();
            sp[tid] += t2;
            __syncthreads();
        }
        if (tid < CB) g_boff[tid] = sp[tid] - v;
    }
    grid_barrier(3);

    // Phase E: local exclusive scan over sdeg + write row/cur
    __shared__ int sp2[128];
    int v2 = (tid < cnt) ? sdeg[tid] : 0;
    if (tid < 128) sp2[tid] = (tid < cnt) ? v2 : 0;
    __syncthreads();
    for (int off = 1; off < 128; off <<= 1) {
        int t2 = (tid >= off && tid < 128) ? sp2[tid - off] : 0;
        __syncthreads();
        if (tid < 128) sp2[tid] += t2;
        __syncthreads();
    }
    int boff = __ldcg(&g_boff[blk]);
    if (tid < cnt) {
        int run = boff + sp2[tid] - v2;
        g_row[lo + tid] = run;
        g_cur[lo + tid] = run;
    }
    if (blk == CB - 1 && tid == 0) g_row[NN] = boff + bsum;
    grid_barrier(4);

    // Phase F: fill CSR
    for (int e = gt; e < E; e += GS) {
        int dst = load_idx(eiv, (long long)E + e);
        if ((unsigned)dst >= NN) continue;
        int src = load_idx(eiv, e);
        int p = atomicAdd(&g_cur[dst], 1);
        if ((unsigned)src < NN) {
            g_srcs[p] = src;
            g_ws[p]   = ew[e];
        } else {                               // keep slot consistent, zero-weight
            g_srcs[p] = 0;
            g_ws[p]   = 0.f;
        }
    }
}

// ---------------- linear: h[n][b][t][c] = sum_ci x[b][ci][n][t] * W[ci][c] (fp16 out) ----------------
__global__ void k_linear(const float* __restrict__ x, const float* __restrict__ W) {
    __shared__ __align__(16) float ws[CC * CC];
    int tid = threadIdx.x;
    for (int i = tid; i < CC * CC; i += blockDim.x) ws[i] = W[i];
    __syncthreads();

    int gid = blockIdx.x * blockDim.x + tid;   // enumerates (b, n, t)
    if (gid >= BNT) return;
    int b = gid / (NN * TT);
    int r = gid % (NN * TT);                   // n*TT + t
    int n = r / TT;
    int t = r % TT;

    const float* xp = x + (size_t)b * CC * NN * TT + r;
    float xv[CC];
#pragma unroll
    for (int c = 0; c < CC; c++) xv[c] = xp[c * (NN * TT)];

    float4 acc[8];
#pragma unroll
    for (int d = 0; d < 8; d++) acc[d] = make_float4(0.f, 0.f, 0.f, 0.f);

    const float4* w4 = (const float4*)ws;      // [c][8] float4 rows of W
#pragma unroll
    for (int c = 0; c < CC; c++) {
        float xc = xv[c];
#pragma unroll
        for (int d = 0; d < 8; d++) {
            float4 w = w4[c * 8 + d];
            acc[d].x = fmaf(xc, w.x, acc[d].x);
            acc[d].y = fmaf(xc, w.y, acc[d].y);
            acc[d].z = fmaf(xc, w.z, acc[d].z);
            acc[d].w = fmaf(xc, w.w, acc[d].w);
        }
    }

    uint4* hp = (uint4*)g_h + ((size_t)n * NB + b) * (FF / 8) + t * 4;
#pragma unroll
    for (int j = 0; j < 4; j++) {
        __half2 p0 = __floats2half2_rn(acc[2 * j].x,     acc[2 * j].y);
        __half2 p1 = __floats2half2_rn(acc[2 * j].z,     acc[2 * j].w);
        __half2 p2 = __floats2half2_rn(acc[2 * j + 1].x, acc[2 * j + 1].y);
        __half2 p3 = __floats2half2_rn(acc[2 * j + 1].z, acc[2 * j + 1].w);
        uint4 o;
        o.x = *reinterpret_cast<unsigned*>(&p0);
        o.y = *reinterpret_cast<unsigned*>(&p1);
        o.z = *reinterpret_cast<unsigned*>(&p2);
        o.w = *reinterpret_cast<unsigned*>(&p3);
        hp[j] = o;
    }
}

// ---------------- gather + fused BN stats ----------------
// One warp per node, all 4 batches. fp16 source, fp32 accum, fp16 agg store.
// Bias intentionally dropped: a per-channel constant shift is exactly cancelled
// by the training-mode BatchNorm that follows (y - mean(y)).
__device__ __forceinline__ void fma8(float2* a, uint4 v, float w) {
    unsigned u[4] = { v.x, v.y, v.z, v.w };
#pragma unroll
    for (int k = 0; k < 4; k++) {
        float2 f = __half22float2(*reinterpret_cast<__half2*>(&u[k]));
        a[k].x = fmaf(w, f.x, a[k].x);
        a[k].y = fmaf(w, f.y, a[k].y);
    }
}

// grid is exactly NN/4 blocks of 128 threads (NN % 4 == 0): no inactive warps.
__global__ __launch_bounds__(128) void k_gather() {
    int n    = (blockIdx.x * blockDim.x + threadIdx.x) >> 5;
    int lane = threadIdx.x & 31;

    float2 acc[24];
#pragma unroll
    for (int k = 0; k < 24; k++) acc[k] = make_float2(0.f, 0.f);

    int e0 = g_row[n], e1 = g_row[n + 1];
    const uint4* hb = (const uint4*)g_h;

    for (int e = e0; e < e1; e++) {
        float w = g_ws[e];
        const uint4* hr = hb + (size_t)g_srcs[e] * NROWU4;
        uint4 v[6];
#pragma unroll
        for (int j = 0; j < 6; j++) v[j] = hr[lane + 32 * j];
#pragma unroll
        for (int j = 0; j < 6; j++) fma8(&acc[j * 4], v[j], w);
    }

    uint4* ap = (uint4*)g_agg + (size_t)n * NROWU4;
#pragma unroll
    for (int j = 0; j < 6; j++) {
        __half2 p0 = __floats2half2_rn(acc[4*j].x,   acc[4*j].y);
        __half2 p1 = __floats2half2_rn(acc[4*j+1].x, acc[4*j+1].y);
        __half2 p2 = __floats2half2_rn(acc[4*j+2].x, acc[4*j+2].y);
        __half2 p3 = __floats2half2_rn(acc[4*j+3].x, acc[4*j+3].y);
        uint4 o;
        o.x = *reinterpret_cast<unsigned*>(&p0);
        o.y = *reinterpret_cast<unsigned*>(&p1);
        o.z = *reinterpret_cast<unsigned*>(&p2);
        o.w = *reinterpret_cast<unsigned*>(&p3);
        ap[lane + 32 * j] = o;
    }

    // fused per-channel stats: this lane covers channels 8*(lane&3)..+7
    float s[8], ss[8];
#pragma unroll
    for (int k = 0; k < 8; k++) { s[k] = 0.f; ss[k] = 0.f; }
#pragma unroll
    for (int j = 0; j < 6; j++) {
#pragma unroll
        for (int m = 0; m < 4; m++) {
            float2 v = acc[4 * j + m];
            s [2*m]   += v.x;  ss[2*m]   += v.x * v.x;
            s [2*m+1] += v.y;  ss[2*m+1] += v.y * v.y;
        }
    }
#pragma unroll
    for (int off = 16; off >= 4; off >>= 1) {
#pragma unroll
        for (int k = 0; k < 8; k++) {
            s [k] += __shfl_xor_sync(0xffffffffu, s [k], off);
            ss[k] += __shfl_xor_sync(0xffffffffu, ss[k], off);
        }
    }
    __shared__ float sb[CC], ssb[CC];
    if (threadIdx.x < CC) { sb[threadIdx.x] = 0.f; ssb[threadIdx.x] = 0.f; }
    __syncthreads();
    if (lane < 4) {
        int cbase = 8 * lane;
#pragma unroll
        for (int k = 0; k < 8; k++) {
            atomicAdd(&sb [cbase + k], s [k]);
            atomicAdd(&ssb[cbase + k], ss[k]);
        }
    }
    __syncthreads();
    if (threadIdx.x < CC) {
        atomicAdd(&g_sum  [threadIdx.x], (double)sb [threadIdx.x]);
        atomicAdd(&g_sumsq[threadIdx.x], (double)ssb[threadIdx.x]);
    }
}

// ---------------- finalize BN params + reset grid-barrier counters ----------------
__global__ void k_final(const float* __restrict__ gamma, const float* __restrict__ beta) {
    int c = threadIdx.x;
    if (c < 8) g_bar[c] = 0;     // ready for next replay (static-zero covers first run)
    if (c < CC) {
        double cnt  = (double)NB * NN * TT;
        double mean = g_sum[c] / cnt;
        double var  = g_sumsq[c] / cnt - mean * mean;
        float sc = gamma[c] * rsqrtf((float)var + 1e-5f);
        g_scale[c] = sc;
        g_shift[c] = beta[c] - (float)mean * sc;
    }
}

// ---------------- transpose + normalize + relu -> out[B][C][N][T] ----------------
#define CHUNK 16
__global__ void k_out(float* __restrict__ out) {
    __shared__ __align__(16) float tile[CHUNK * TT * 33];
    __shared__ float sc[CC], sf[CC];
    int b     = blockIdx.x / (NN / CHUNK);
    int chunk = blockIdx.x % (NN / CHUNK);
    int n0 = chunk * CHUNK;
    int tid = threadIdx.x;
    if (tid < CC) { sc[tid] = g_scale[tid]; sf[tid] = g_shift[tid]; }

    for (int p = tid; p < CHUNK * FF / 2; p += 256) {
        int i  = 2 * p;
        int nd = i / FF;
        int f  = i % FF;
        __half2 hv = *(const __half2*)&g_agg[((size_t)(n0 + nd) * NB + b) * FF + f];
        float2 fv = __half22float2(hv);
        int row = i >> 5, col = i & 31;
        tile[row * 33 + col]     = fv.x;
        tile[row * 33 + col + 1] = fv.y;
    }
    __syncthreads();

    float* ob = out + (size_t)b * CC * NN * TT + n0 * TT;
    const int JD = CHUNK * TT;  // 192
    for (int i = tid; i < CHUNK * FF; i += 256) {
        int c = i / JD;
        int j = i % JD;
        float v = fmaf(tile[j * 33 + c], sc[c], sf[c]);
        ob[(size_t)c * NN * TT + j] = fmaxf(v, 0.f);
    }
}

extern "C" void kernel_launch(void* const* d_in, const int* in_sizes, int n_in,
                              void* d_out, int out_size) {
    const float* x     = (const float*)d_in[0];
    const void*  ei    = (const void*)d_in[1];
    const float* ew    = (const float*)d_in[2];
    const float* W     = (const float*)d_in[3];
    const float* gamma = (const float*)d_in[5];
    const float* beta  = (const float*)d_in[6];
    float* out = (float*)d_out;

    int E = in_sizes[2];   // edge_weight element count == E

    static cudaStream_t s2 = nullptr;
    static cudaEvent_t evFork = nullptr, evJoin = nullptr;
    if (s2 == nullptr) {
        cudaStreamCreateWithFlags(&s2, cudaStreamNonBlocking);
        cudaEventCreateWithFlags(&evFork, cudaEventDisableTiming);
        cudaEventCreateWithFlags(&evJoin, cudaEventDisableTiming);
    }

    // Fork: k_linear (independent of the CSR chain) overlaps with k_csr.
    cudaEventRecord(evFork, 0);
    cudaStreamWaitEvent(s2, evFork, 0);
    k_linear<<<(BNT + 255) / 256, 256, 0, s2>>>(x, W);
    cudaEventRecord(evJoin, s2);

    // Fused CSR build on the main stream.
    k_csr<<<CB, 256>>>(ei, ew, E);

    // Join: gather needs g_h (s2) and the CSR arrays (main stream).
    cudaStreamWaitEvent(0, evJoin, 0);
    k_gather<<<NN / 4, 128>>>();
    k_final<<<1, 32>>>(gamma, beta);
    k_out<<<NB * (NN / CHUNK), 256>>>(out);
}